// round 2
// baseline (speedup 1.0000x reference)
#include <cuda_runtime.h>
#include <cuda_bf16.h>
#include <math.h>

// ControlNorm2D: B=32, C=256, H=64, W=64
// out[b,c,h,w] = (x[b,c,h,w] - mu_stale[b,c]) / sqrt(var_stale[b,c] + eps)
// mu_stale / var_stale come from two cross-batch EMA recurrences (lin_momentum).
//
// 3 kernels:
//   1. stats:     per-(b,c) mean + E[x^2] reduction (HBM-bound, 134 MB read)
//   2. recur:     one thread per channel; both lin_momentum recurrences with
//                 DIRECT 32-wide window dot products (matches ref einsum exactly)
//   3. normalize: elementwise (x - mu)*inv_scale (HBM-bound, 268 MB)

#define B_ 32
#define C_ 256
#define HW_ 4096          // 64*64
#define BC_ (B_ * C_)     // 8192

static __device__ float g_mu[BC_];    // per-(b,c) spatial mean
static __device__ float g_v[BC_];     // per-(b,c) spatial variance
static __device__ float g_mub[BC_];   // stale EMA mean (_mu_b)
static __device__ float g_inv[BC_];   // 1/sqrt(_var_b + eps)

// ---------------------------------------------------------------------------
// Kernel 1: per-(b,c) mean and E[x^2]. One block per (b,c) slice.
// 256 threads x 4 float4 = 4096 floats.
// ---------------------------------------------------------------------------
__global__ __launch_bounds__(256) void stats_kernel(const float* __restrict__ x) {
    const int bc  = blockIdx.x;
    const int tid = threadIdx.x;
    const float4* xp = reinterpret_cast<const float4*>(x) + (size_t)bc * (HW_ / 4);

    float s = 0.f, ss = 0.f;
#pragma unroll
    for (int i = 0; i < 4; ++i) {
        float4 v = xp[i * 256 + tid];
        s  += (v.x + v.y) + (v.z + v.w);
        ss += v.x * v.x + v.y * v.y + v.z * v.z + v.w * v.w;
    }

    // warp reduce
#pragma unroll
    for (int o = 16; o > 0; o >>= 1) {
        s  += __shfl_down_sync(0xffffffffu, s,  o);
        ss += __shfl_down_sync(0xffffffffu, ss, o);
    }

    __shared__ float sh_s[8], sh_ss[8];
    const int w = tid >> 5, l = tid & 31;
    if (l == 0) { sh_s[w] = s; sh_ss[w] = ss; }
    __syncthreads();

    if (w == 0) {
        s  = (l < 8) ? sh_s[l]  : 0.f;
        ss = (l < 8) ? sh_ss[l] : 0.f;
#pragma unroll
        for (int o = 4; o > 0; o >>= 1) {
            s  += __shfl_down_sync(0xffffffffu, s,  o);
            ss += __shfl_down_sync(0xffffffffu, ss, o);
        }
        if (l == 0) {
            const float inv_n = 1.f / (float)HW_;
            float mu = s * inv_n;
            g_mu[bc] = mu;
            g_v[bc]  = ss * inv_n - mu * mu;
        }
    }
}

// ---------------------------------------------------------------------------
// Kernel 2: lin_momentum x2 per channel. One block, 256 threads, thread c
// handles channel c. Window sums computed as direct dot products to mirror
// the reference einsum's accumulation structure (no sliding-sum drift).
//   tmp[i] = sum_j pw[j] * seq[i+j],  pw[j] = AF^(31-j)
//   new[i] = AF^32 * stream[i] + (1-AF) * tmp[i]
//   stale[0] = stream[B-1]; stale[i] = new[i-1]
// ---------------------------------------------------------------------------
__global__ __launch_bounds__(256) void recur_kernel(
    const float* __restrict__ m,      // stream for mean EMA  [B,C]
    const float* __restrict__ var,    // stream for var EMA   [B,C]
    const float* __restrict__ m_p,    // prev for mean EMA    [B,C]
    const float* __restrict__ var_p)  // prev for var EMA     [B,C]
{
    const int c = threadIdx.x;                    // channel, C_=256=blockDim
    const float AF   = 0.999f;
    const float OMA  = (float)(1.0 - 0.999);      // matches ref (double->f32)
    // AF^32 folded in double at compile time
    const float AFB  = (float)(0.999 * 0.999 * 0.999 * 0.999 * 0.999 * 0.999 * 0.999 * 0.999 *
                               0.999 * 0.999 * 0.999 * 0.999 * 0.999 * 0.999 * 0.999 * 0.999 *
                               0.999 * 0.999 * 0.999 * 0.999 * 0.999 * 0.999 * 0.999 * 0.999 *
                               0.999 * 0.999 * 0.999 * 0.999 * 0.999 * 0.999 * 0.999 * 0.999);
    const float EPSV = 1e-5f;

    // pw[j] = AF^(31-j)
    float pw[B_];
    pw[B_ - 1] = 1.f;
#pragma unroll
    for (int j = B_ - 2; j >= 0; --j) pw[j] = pw[j + 1] * AF;

    // ---------- phase A: mean EMA ----------
    float seq1[2 * B_ - 1];
#pragma unroll
    for (int k = 0; k < B_ - 1; ++k) seq1[k] = m_p[(k + 1) * C_ + c];
#pragma unroll
    for (int k = 0; k < B_; ++k)     seq1[B_ - 1 + k] = g_mu[k * C_ + c];

    float seq2[2 * B_ - 1];   // [0..30] = var_p[1..31], [31..62] = var_current
#pragma unroll
    for (int k = 0; k < B_ - 1; ++k) seq2[k] = var_p[(k + 1) * C_ + c];

    float prev_new = 0.f;
    const float m_last = m[(B_ - 1) * C_ + c];
#pragma unroll
    for (int i = 0; i < B_; ++i) {
        float tmp = 0.f;
#pragma unroll
        for (int j = 0; j < B_; ++j) tmp += pw[j] * seq1[i + j];

        float nw    = AFB * m[i * C_ + c] + OMA * tmp;
        float stale = (i == 0) ? m_last : prev_new;   // _mu_b[i]
        prev_new    = nw;
        g_mub[i * C_ + c] = stale;

        float d = seq1[B_ - 1 + i] - stale;           // mu[i] - _mu_b[i]
        seq2[B_ - 1 + i] = g_v[i * C_ + c] + AF * d * d;   // var_current[i]
    }

    // ---------- phase B: var EMA ----------
    prev_new = 0.f;
    const float var_last = var[(B_ - 1) * C_ + c];
#pragma unroll
    for (int i = 0; i < B_; ++i) {
        float tmp = 0.f;
#pragma unroll
        for (int j = 0; j < B_; ++j) tmp += pw[j] * seq2[i + j];

        float nw    = AFB * var[i * C_ + c] + OMA * tmp;
        float stale = (i == 0) ? var_last : prev_new;   // _var_b[i]
        prev_new    = nw;
        g_inv[i * C_ + c] = 1.f / sqrtf(stale + EPSV);
    }
}

// ---------------------------------------------------------------------------
// Kernel 3: normalize. One block per (b,c), float4 vectorized.
// ---------------------------------------------------------------------------
__global__ __launch_bounds__(256) void norm_kernel(const float* __restrict__ x,
                                                   float* __restrict__ out) {
    const int bc  = blockIdx.x;
    const int tid = threadIdx.x;
    const float mu  = g_mub[bc];
    const float inv = g_inv[bc];

    const float4* xp = reinterpret_cast<const float4*>(x) + (size_t)bc * (HW_ / 4);
    float4*       op = reinterpret_cast<float4*>(out)     + (size_t)bc * (HW_ / 4);

#pragma unroll
    for (int i = 0; i < 4; ++i) {
        float4 v = xp[i * 256 + tid];
        v.x = (v.x - mu) * inv;
        v.y = (v.y - mu) * inv;
        v.z = (v.z - mu) * inv;
        v.w = (v.w - mu) * inv;
        op[i * 256 + tid] = v;
    }
}

// ---------------------------------------------------------------------------
extern "C" void kernel_launch(void* const* d_in, const int* in_sizes, int n_in,
                              void* d_out, int out_size) {
    const float* x     = (const float*)d_in[0];
    const float* m     = (const float*)d_in[1];
    const float* var   = (const float*)d_in[2];
    const float* m_p   = (const float*)d_in[3];
    const float* var_p = (const float*)d_in[4];
    float* out = (float*)d_out;

    stats_kernel<<<BC_, 256>>>(x);
    recur_kernel<<<1, C_>>>(m, var, m_p, var_p);
    norm_kernel<<<BC_, 256>>>(x, out);
}

// round 4
// speedup vs baseline: 1.1328x; 1.1328x over previous
#include <cuda_runtime.h>
#include <cuda_bf16.h>
#include <math.h>

// ControlNorm2D: B=32, C=256, H=64, W=64
// out[b,c,h,w] = (x[b,c,h,w] - mu_stale[b,c]) / sqrt(var_stale[b,c] + eps)
//
// R4 (= R3 untested + norm MLP deepening):
//  - stats: 2 slices/block, 8 independent LDG.128 per thread
//  - norm:  2 slices/block (8 LDG.128 in flight), REVERSE bc order to chase
//           stats' L2-resident tail of x, __stcs streaming stores for out

#define B_ 32
#define C_ 256
#define HW_ 4096          // 64*64
#define BC_ (B_ * C_)     // 8192

static __device__ float g_mu[BC_];    // per-(b,c) spatial mean
static __device__ float g_v[BC_];     // per-(b,c) spatial variance
static __device__ float g_mub[BC_];   // stale EMA mean (_mu_b)
static __device__ float g_inv[BC_];   // 1/sqrt(_var_b + eps)

// ---------------------------------------------------------------------------
// Kernel 1: per-(b,c) mean and E[x^2]. One block per TWO (b,c) slices.
// ---------------------------------------------------------------------------
__global__ __launch_bounds__(256) void stats_kernel(const float* __restrict__ x) {
    const int bc0 = blockIdx.x * 2;
    const int tid = threadIdx.x;
    const float4* xp = reinterpret_cast<const float4*>(x) + (size_t)bc0 * (HW_ / 4);

    float4 r[8];
#pragma unroll
    for (int i = 0; i < 8; ++i)            // 8 independent 16B loads in flight
        r[i] = xp[i * 256 + tid];

    float s0 = 0.f, ss0 = 0.f, s1 = 0.f, ss1 = 0.f;
#pragma unroll
    for (int i = 0; i < 4; ++i) {
        float4 v = r[i];
        s0  += (v.x + v.y) + (v.z + v.w);
        ss0 += v.x * v.x + v.y * v.y + v.z * v.z + v.w * v.w;
        float4 w = r[i + 4];
        s1  += (w.x + w.y) + (w.z + w.w);
        ss1 += w.x * w.x + w.y * w.y + w.z * w.z + w.w * w.w;
    }

#pragma unroll
    for (int o = 16; o > 0; o >>= 1) {
        s0  += __shfl_down_sync(0xffffffffu, s0,  o);
        ss0 += __shfl_down_sync(0xffffffffu, ss0, o);
        s1  += __shfl_down_sync(0xffffffffu, s1,  o);
        ss1 += __shfl_down_sync(0xffffffffu, ss1, o);
    }

    __shared__ float sh[4][8];
    const int w = tid >> 5, l = tid & 31;
    if (l == 0) { sh[0][w] = s0; sh[1][w] = ss0; sh[2][w] = s1; sh[3][w] = ss1; }
    __syncthreads();

    if (w == 0) {
        s0  = (l < 8) ? sh[0][l] : 0.f;
        ss0 = (l < 8) ? sh[1][l] : 0.f;
        s1  = (l < 8) ? sh[2][l] : 0.f;
        ss1 = (l < 8) ? sh[3][l] : 0.f;
#pragma unroll
        for (int o = 4; o > 0; o >>= 1) {
            s0  += __shfl_down_sync(0xffffffffu, s0,  o);
            ss0 += __shfl_down_sync(0xffffffffu, ss0, o);
            s1  += __shfl_down_sync(0xffffffffu, s1,  o);
            ss1 += __shfl_down_sync(0xffffffffu, ss1, o);
        }
        if (l == 0) {
            const float inv_n = 1.f / (float)HW_;
            float mu0 = s0 * inv_n;
            g_mu[bc0]     = mu0;
            g_v[bc0]      = ss0 * inv_n - mu0 * mu0;
            float mu1 = s1 * inv_n;
            g_mu[bc0 + 1] = mu1;
            g_v[bc0 + 1]  = ss1 * inv_n - mu1 * mu1;
        }
    }
}

// ---------------------------------------------------------------------------
// Kernel 2: lin_momentum x2 per channel, one thread per channel, window sums
// as direct 32-wide dot products (mirrors the reference einsum exactly).
// ---------------------------------------------------------------------------
__global__ __launch_bounds__(256) void recur_kernel(
    const float* __restrict__ m,
    const float* __restrict__ var,
    const float* __restrict__ m_p,
    const float* __restrict__ var_p)
{
    const int c = threadIdx.x;
    const float AF   = 0.999f;
    const float OMA  = (float)(1.0 - 0.999);      // matches ref (double->f32)
    const float AFB  = (float)(0.999 * 0.999 * 0.999 * 0.999 * 0.999 * 0.999 * 0.999 * 0.999 *
                               0.999 * 0.999 * 0.999 * 0.999 * 0.999 * 0.999 * 0.999 * 0.999 *
                               0.999 * 0.999 * 0.999 * 0.999 * 0.999 * 0.999 * 0.999 * 0.999 *
                               0.999 * 0.999 * 0.999 * 0.999 * 0.999 * 0.999 * 0.999 * 0.999);
    const float EPSV = 1e-5f;

    float pw[B_];                      // pw[j] = AF^(31-j)
    pw[B_ - 1] = 1.f;
#pragma unroll
    for (int j = B_ - 2; j >= 0; --j) pw[j] = pw[j + 1] * AF;

    // ---------- phase A: mean EMA ----------
    float seq1[2 * B_ - 1];
#pragma unroll
    for (int k = 0; k < B_ - 1; ++k) seq1[k] = m_p[(k + 1) * C_ + c];
#pragma unroll
    for (int k = 0; k < B_; ++k)     seq1[B_ - 1 + k] = g_mu[k * C_ + c];

    float seq2[2 * B_ - 1];
#pragma unroll
    for (int k = 0; k < B_ - 1; ++k) seq2[k] = var_p[(k + 1) * C_ + c];

    float prev_new = 0.f;
    const float m_last = m[(B_ - 1) * C_ + c];
#pragma unroll
    for (int i = 0; i < B_; ++i) {
        float tmp = 0.f;
#pragma unroll
        for (int j = 0; j < B_; ++j) tmp += pw[j] * seq1[i + j];

        float nw    = AFB * m[i * C_ + c] + OMA * tmp;
        float stale = (i == 0) ? m_last : prev_new;
        prev_new    = nw;
        g_mub[i * C_ + c] = stale;

        float d = seq1[B_ - 1 + i] - stale;
        seq2[B_ - 1 + i] = g_v[i * C_ + c] + AF * d * d;
    }

    // ---------- phase B: var EMA ----------
    prev_new = 0.f;
    const float var_last = var[(B_ - 1) * C_ + c];
#pragma unroll
    for (int i = 0; i < B_; ++i) {
        float tmp = 0.f;
#pragma unroll
        for (int j = 0; j < B_; ++j) tmp += pw[j] * seq2[i + j];

        float nw    = AFB * var[i * C_ + c] + OMA * tmp;
        float stale = (i == 0) ? var_last : prev_new;
        prev_new    = nw;
        g_inv[i * C_ + c] = 1.f / sqrtf(stale + EPSV);
    }
}

// ---------------------------------------------------------------------------
// Kernel 3: normalize. TWO slices per block, reverse order over slice pairs
// (chases stats' L2-resident tail of x); streaming stores for out.
// ---------------------------------------------------------------------------
__global__ __launch_bounds__(256) void norm_kernel(const float* __restrict__ x,
                                                   float* __restrict__ out) {
    const int pair = (BC_ / 2 - 1) - blockIdx.x;    // reverse pair order
    const int bc0  = pair * 2;
    const int tid  = threadIdx.x;
    const float mu0  = g_mub[bc0],     inv0 = g_inv[bc0];
    const float mu1  = g_mub[bc0 + 1], inv1 = g_inv[bc0 + 1];

    const float4* xp = reinterpret_cast<const float4*>(x) + (size_t)bc0 * (HW_ / 4);
    float4*       op = reinterpret_cast<float4*>(out)     + (size_t)bc0 * (HW_ / 4);

    float4 r[8];
#pragma unroll
    for (int i = 0; i < 8; ++i)            // 8 independent 16B loads in flight
        r[i] = xp[i * 256 + tid];

#pragma unroll
    for (int i = 0; i < 8; ++i) {
        const float mu  = (i < 4) ? mu0  : mu1;
        const float inv = (i < 4) ? inv0 : inv1;
        float4 v = r[i];
        v.x = (v.x - mu) * inv;
        v.y = (v.y - mu) * inv;
        v.z = (v.z - mu) * inv;
        v.w = (v.w - mu) * inv;
        __stcs(&op[i * 256 + tid], v);     // evict-first: don't kill x in L2
    }
}

// ---------------------------------------------------------------------------
extern "C" void kernel_launch(void* const* d_in, const int* in_sizes, int n_in,
                              void* d_out, int out_size) {
    const float* x     = (const float*)d_in[0];
    const float* m     = (const float*)d_in[1];
    const float* var   = (const float*)d_in[2];
    const float* m_p   = (const float*)d_in[3];
    const float* var_p = (const float*)d_in[4];
    float* out = (float*)d_out;

    stats_kernel<<<BC_ / 2, 256>>>(x);
    recur_kernel<<<1, C_>>>(m, var, m_p, var_p);
    norm_kernel<<<BC_ / 2, 256>>>(x, out);
}